// round 2
// baseline (speedup 1.0000x reference)
#include <cuda_runtime.h>
#include <math.h>

// Problem constants
#define BB 256   // batch
#define TT 512   // timesteps
#define II 128   // input dim
#define HH 256   // hidden dim
#define GG 1024  // 4*H gate rows
#define CC 1000  // classes

// Tiling
#define MT 64      // batch tile per CTA
#define UT 16      // hidden units per CTA  -> 64 gate rows
#define KC 32      // K chunk
#define NTHREADS 128

// Persistent state (double-buffered h per layer; c updated in place)
__device__ float g_h0[2][BB][HH];
__device__ float g_c0[BB][HH];
__device__ float g_h1[2][BB][HH];
__device__ float g_c1[BB][HH];

__device__ __forceinline__ float sigmoidf_(float x) {
    return 1.0f / (1.0f + expf(-x));
}

__global__ void init_states() {
    int idx = blockIdx.x * blockDim.x + threadIdx.x;
    int stride = gridDim.x * blockDim.x;
    float* h0 = &g_h0[0][0][0];
    float* h1 = &g_h1[0][0][0];
    float* c0 = &g_c0[0][0];
    float* c1 = &g_c1[0][0];
    for (int i = idx; i < 2 * BB * HH; i += stride) { h0[i] = 0.f; h1[i] = 0.f; }
    for (int i = idx; i < BB * HH; i += stride) { c0[i] = 0.f; c1[i] = 0.f; }
}

// One pipelined launch: blocks [0,64) do layer0 step t; blocks [64,128) do layer1 step t-1.
__global__ __launch_bounds__(NTHREADS) void lstm_step(
    int t,
    const float* __restrict__ x,
    const float* __restrict__ Wih0, const float* __restrict__ Whh0,
    const float* __restrict__ bih0, const float* __restrict__ bhh0,
    const float* __restrict__ Wih1, const float* __restrict__ Whh1,
    const float* __restrict__ bih1, const float* __restrict__ bhh1)
{
    const int bx = blockIdx.x;
    const bool is_l1 = (bx >= 64);
    if (!is_l1 && t == TT) return;   // layer0 done after step TT-1
    if (is_l1 && t == 0) return;     // layer1 starts at launch 1

    const int lb = bx & 63;
    const int mt = lb >> 4;   // 0..3  batch tile
    const int nt = lb & 15;   // 0..15 unit tile

    // Per-layer configuration
    const float* aseg0;  size_t astride0; int K0;
    const float* aseg1;  size_t astride1; int K1;
    const float* W0; size_t wstride0;
    const float* W1; size_t wstride1;
    const float* bih; const float* bhh;
    const float* hin; float* hout; float* cbuf;

    if (!is_l1) {
        // layer0, step s = t
        int par = t & 1;
        hin  = &g_h0[par][0][0];
        hout = &g_h0[par ^ 1][0][0];
        cbuf = &g_c0[0][0];
        aseg0 = x + (size_t)t * II;  astride0 = (size_t)TT * II; K0 = II;
        aseg1 = hin;                 astride1 = HH;              K1 = HH;
        W0 = Wih0; wstride0 = II;
        W1 = Whh0; wstride1 = HH;
        bih = bih0; bhh = bhh0;
    } else {
        // layer1, step s = t - 1
        int s = t - 1;
        int sp = s & 1;
        const float* in0 = &g_h0[t & 1][0][0];  // layer0 output after step s
        hin  = &g_h1[sp][0][0];
        hout = &g_h1[sp ^ 1][0][0];
        cbuf = &g_c1[0][0];
        aseg0 = in0; astride0 = HH; K0 = HH;
        aseg1 = hin; astride1 = HH; K1 = HH;
        W0 = Wih1; wstride0 = HH;
        W1 = Whh1; wstride1 = HH;
        bih = bih1; bhh = bhh1;
    }

    __shared__ float As[MT][KC + 1];
    __shared__ float Ws[64][KC + 1];

    const int tid = threadIdx.x;
    const int tx = tid & 7;    // unit-pair index  (units 2*tx, 2*tx+1 local)
    const int ty = tid >> 3;   // batch group      (rows 4*ty .. 4*ty+3 local)

    float acc[8][4];
#pragma unroll
    for (int g = 0; g < 8; g++)
#pragma unroll
        for (int i = 0; i < 4; i++) acc[g][i] = 0.f;

    const int nch = (K0 + K1) / KC;
    for (int c = 0; c < nch; c++) {
        int kglob = c * KC;
        const float* aptr; size_t astr; int koff;
        const float* wptr; size_t wstr;
        if (kglob < K0) {
            aptr = aseg0; astr = astride0; koff = kglob;
            wptr = W0; wstr = wstride0;
        } else {
            aptr = aseg1; astr = astride1; koff = kglob - K0;
            wptr = W1; wstr = wstride1;
        }

        __syncthreads();
        // Load A tile [64 x KC]
#pragma unroll
        for (int i = tid; i < MT * KC; i += NTHREADS) {
            int bl = i >> 5;
            int k  = i & (KC - 1);
            As[bl][k] = aptr[(size_t)(mt * MT + bl) * astr + koff + k];
        }
        // Load W tile [64 gate rows x KC]
#pragma unroll
        for (int i = tid; i < 64 * KC; i += NTHREADS) {
            int r = i >> 5;
            int k = i & (KC - 1);
            int gate = r >> 4;
            int ul = r & 15;
            int grow = gate * HH + nt * UT + ul;
            Ws[r][k] = wptr[(size_t)grow * wstr + koff + k];
        }
        __syncthreads();

#pragma unroll 8
        for (int kk = 0; kk < KC; kk++) {
            float a0 = As[ty * 4 + 0][kk];
            float a1 = As[ty * 4 + 1][kk];
            float a2 = As[ty * 4 + 2][kk];
            float a3 = As[ty * 4 + 3][kk];
            float w[8];
#pragma unroll
            for (int g = 0; g < 4; g++) {
#pragma unroll
                for (int j = 0; j < 2; j++)
                    w[g * 2 + j] = Ws[g * 16 + tx * 2 + j][kk];
            }
#pragma unroll
            for (int g = 0; g < 8; g++) {
                acc[g][0] = fmaf(w[g], a0, acc[g][0]);
                acc[g][1] = fmaf(w[g], a1, acc[g][1]);
                acc[g][2] = fmaf(w[g], a2, acc[g][2]);
                acc[g][3] = fmaf(w[g], a3, acc[g][3]);
            }
        }
    }

    // Epilogue: gates -> activations -> state update
#pragma unroll
    for (int j = 0; j < 2; j++) {
        int ug = nt * UT + tx * 2 + j;               // global hidden unit
        float bi = bih[ug]            + bhh[ug];
        float bf = bih[HH + ug]       + bhh[HH + ug];
        float bg = bih[2 * HH + ug]   + bhh[2 * HH + ug];
        float bo = bih[3 * HH + ug]   + bhh[3 * HH + ug];
#pragma unroll
        for (int i = 0; i < 4; i++) {
            int bglob = mt * MT + ty * 4 + i;
            float ig = sigmoidf_(acc[0 * 2 + j][i] + bi);
            float fg = sigmoidf_(acc[1 * 2 + j][i] + bf);
            float gg = tanhf    (acc[2 * 2 + j][i] + bg);
            float og = sigmoidf_(acc[3 * 2 + j][i] + bo);
            size_t off = (size_t)bglob * HH + ug;
            float cn = fg * cbuf[off] + ig * gg;
            cbuf[off] = cn;
            hout[off] = og * tanhf(cn);
        }
    }
}

// out[b][c] = dot(h1_final[b], fcW[c]) + fcb[c]
__global__ void classifier_kernel(const float* __restrict__ fcW,
                                  const float* __restrict__ fcb,
                                  float* __restrict__ out)
{
    __shared__ float hs[HH];
    int b = blockIdx.x;
    for (int i = threadIdx.x; i < HH; i += blockDim.x)
        hs[i] = g_h1[0][b][i];   // after step 511 (sp=1), hout = g_h1[0]
    __syncthreads();

    int warp = threadIdx.x >> 5;
    int lane = threadIdx.x & 31;
    for (int c = warp; c < CC; c += 8) {
        float sum = 0.f;
        const float* wrow = fcW + (size_t)c * HH;
#pragma unroll
        for (int k = lane; k < HH; k += 32)
            sum += hs[k] * wrow[k];
#pragma unroll
        for (int off = 16; off; off >>= 1)
            sum += __shfl_xor_sync(0xffffffffu, sum, off);
        if (lane == 0)
            out[(size_t)b * CC + c] = sum + fcb[c];
    }
}

extern "C" void kernel_launch(void* const* d_in, const int* in_sizes, int n_in,
                              void* d_out, int out_size)
{
    const float* x    = (const float*)d_in[0];
    const float* Wih0 = (const float*)d_in[1];
    const float* Whh0 = (const float*)d_in[2];
    const float* bih0 = (const float*)d_in[3];
    const float* bhh0 = (const float*)d_in[4];
    const float* Wih1 = (const float*)d_in[5];
    const float* Whh1 = (const float*)d_in[6];
    const float* bih1 = (const float*)d_in[7];
    const float* bhh1 = (const float*)d_in[8];
    const float* fcW  = (const float*)d_in[9];
    const float* fcb  = (const float*)d_in[10];
    float* out = (float*)d_out;

    init_states<<<256, 256>>>();

    // Pipelined: launch t runs layer0 step t and layer1 step t-1.
    for (int t = 0; t <= TT; t++) {
        lstm_step<<<128, NTHREADS>>>(t, x, Wih0, Whh0, bih0, bhh0,
                                     Wih1, Whh1, bih1, bhh1);
    }

    classifier_kernel<<<BB, 256>>>(fcW, fcb, out);
}

// round 3
// speedup vs baseline: 1.1959x; 1.1959x over previous
#include <cuda_runtime.h>
#include <math.h>

#define BB 256   // batch
#define TT 512   // timesteps
#define II 128   // input dim
#define HH 256   // hidden dim
#define CC 1000  // classes

#define NCTA 128
#define NTHREADS 256
#define KC 32

// Persistent state (double-buffered h per layer; c updated in place)
__device__ float g_h0[2][BB][HH];
__device__ float g_c0[BB][HH];
__device__ float g_h1[2][BB][HH];
__device__ float g_c1[BB][HH];

// Grid barrier state
__device__ unsigned int g_bar_count = 0;
__device__ unsigned int g_bar_gen = 0;

__device__ __forceinline__ float sigmoidf_(float x) {
    return 1.0f / (1.0f + __expf(-x));
}

__device__ __forceinline__ void grid_barrier() {
    __syncthreads();
    if (threadIdx.x == 0) {
        __threadfence();
        unsigned int gen = g_bar_gen;
        unsigned int t = atomicAdd(&g_bar_count, 1u);
        if (t == NCTA - 1) {
            g_bar_count = 0;
            __threadfence();
            atomicExch(&g_bar_gen, gen + 1);
        } else {
            volatile unsigned int* p = &g_bar_gen;
            while (*p == gen) { __nanosleep(64); }
        }
        __threadfence();
    }
    __syncthreads();
}

struct Smem {
    float As[2][KC * 34];   // transposed [k][b_local], pad row to 34 floats
    float Ws[2][KC * 64];   // transposed [k][slot], slot=u*4+g, XOR-swizzled
};

// One GEMM+activation phase: out tile = 32 batches x 16 units (64 gate rows).
// A = concat(seg0[K0], seg1[HH]); W = concat(W0 rows len w0len, W1 rows len HH).
__device__ __forceinline__ void lstm_phase(
    Smem* sm,
    const float* __restrict__ A0, long a0str, int K0,
    const float* __restrict__ A1,
    const float* __restrict__ W0, int w0len,
    const float* __restrict__ W1,
    float* __restrict__ cbuf, float* __restrict__ hout,
    const float* bias,      // 4 per-thread gate biases (registers)
    int KTOT,
    int tid, int bt, int ut, int u, int bq, int b0, int ug)
{
    // staging-role indices
    const int a_b   = bt * 32 + (tid >> 3);  // global batch this thread stages
    const int s_b   = tid >> 3;              // local batch 0..31
    const int a_k4  = tid & 7;               // A f4 index within chunk
    const int slot  = tid >> 2;              // local W slot 0..63 (= u*4+g)
    const int su    = slot >> 2;
    const int sg    = slot & 3;
    const int srow  = sg * HH + ut * 16 + su; // global weight row
    const int f0    = (tid & 3) * 2;          // W f4 pair base 0..7

    float4 va, wa, wb;
    // prologue: load chunk 0 into registers
    {
        int k = a_k4 * 4;
        const float* src = (k < K0) ? (A0 + (long)a_b * a0str + k)
                                    : (A1 + (long)a_b * HH + (k - K0));
        va = __ldcg((const float4*)src);
        int kw = f0 * 4;
        const float* wsrc = (kw < K0) ? (W0 + (long)srow * w0len + kw)
                                      : (W1 + (long)srow * HH + (kw - K0));
        wa = *(const float4*)wsrc;
        wb = *(const float4*)(wsrc + 4);
    }

    float acc[2][4];
#pragma unroll
    for (int i = 0; i < 2; i++)
#pragma unroll
        for (int g = 0; g < 4; g++) acc[i][g] = 0.f;

    const int nch = KTOT / KC;
    int p = 0;
    for (int c = 0; c < nch; c++) {
        float* Asp = sm->As[p];
        float* Wsp = sm->Ws[p];
        // store staged chunk (transposed; W XOR-swizzled by k's f4 index)
#pragma unroll
        for (int j = 0; j < 4; j++)
            Asp[(a_k4 * 4 + j) * 34 + s_b] = ((float*)&va)[j];
#pragma unroll
        for (int j = 0; j < 4; j++) {
            int k = f0 * 4 + j;
            Wsp[(k * 16 + (su ^ f0)) * 4 + sg] = ((float*)&wa)[j];
        }
#pragma unroll
        for (int j = 0; j < 4; j++) {
            int k = (f0 + 1) * 4 + j;
            Wsp[(k * 16 + (su ^ (f0 + 1))) * 4 + sg] = ((float*)&wb)[j];
        }
        __syncthreads();
        // prefetch chunk c+1 into registers (hidden under compute)
        if (c + 1 < nch) {
            int kb = (c + 1) * KC;
            int k = kb + a_k4 * 4;
            const float* src = (k < K0) ? (A0 + (long)a_b * a0str + k)
                                        : (A1 + (long)a_b * HH + (k - K0));
            va = __ldcg((const float4*)src);
            int kw = kb + f0 * 4;
            const float* wsrc = (kw < K0) ? (W0 + (long)srow * w0len + kw)
                                          : (W1 + (long)srow * HH + (kw - K0));
            wa = *(const float4*)wsrc;
            wb = *(const float4*)(wsrc + 4);
        }
        // compute chunk
#pragma unroll
        for (int k = 0; k < KC; k++) {
            float2 a2 = *(const float2*)&Asp[k * 34 + bq * 2];
            float4 w4 = *(const float4*)&Wsp[(k * 16 + (u ^ (k >> 2))) * 4];
            acc[0][0] = fmaf(w4.x, a2.x, acc[0][0]);
            acc[0][1] = fmaf(w4.y, a2.x, acc[0][1]);
            acc[0][2] = fmaf(w4.z, a2.x, acc[0][2]);
            acc[0][3] = fmaf(w4.w, a2.x, acc[0][3]);
            acc[1][0] = fmaf(w4.x, a2.y, acc[1][0]);
            acc[1][1] = fmaf(w4.y, a2.y, acc[1][1]);
            acc[1][2] = fmaf(w4.z, a2.y, acc[1][2]);
            acc[1][3] = fmaf(w4.w, a2.y, acc[1][3]);
        }
        p ^= 1;
    }

    // epilogue: activations + state update (thread owns 2 batches x 1 unit)
#pragma unroll
    for (int i = 0; i < 2; i++) {
        long off = (long)(b0 + i) * HH + ug;
        float ig = sigmoidf_(acc[i][0] + bias[0]);
        float fg = sigmoidf_(acc[i][1] + bias[1]);
        float gg = tanhf(acc[i][2] + bias[2]);
        float og = sigmoidf_(acc[i][3] + bias[3]);
        float cn = fg * cbuf[off] + ig * gg;
        cbuf[off] = cn;
        hout[off] = og * tanhf(cn);
    }
}

__global__ __launch_bounds__(NTHREADS, 1) void lstm_persistent(
    const float* __restrict__ x,
    const float* __restrict__ Wih0, const float* __restrict__ Whh0,
    const float* __restrict__ bih0, const float* __restrict__ bhh0,
    const float* __restrict__ Wih1, const float* __restrict__ Whh1,
    const float* __restrict__ bih1, const float* __restrict__ bhh1)
{
    __shared__ Smem sm;

    const int tid = threadIdx.x;
    const int cid = blockIdx.x;
    const int bt = cid >> 4;     // batch tile (32 batches)
    const int ut = cid & 15;     // unit tile (16 units)

    // compute-role indices
    const int u  = tid & 15;             // unit within tile
    const int bq = tid >> 4;             // 0..15 -> batches 2bq, 2bq+1
    const int b0 = bt * 32 + bq * 2;
    const int ug = ut * 16 + u;          // global hidden unit

    // biases held in registers for all 512 steps
    float bias0[4], bias1[4];
#pragma unroll
    for (int g = 0; g < 4; g++) {
        bias0[g] = bih0[g * HH + ug] + bhh0[g * HH + ug];
        bias1[g] = bih1[g * HH + ug] + bhh1[g * HH + ug];
    }

    // zero owned state (each (b, unit) owned by exactly one thread grid-wide)
#pragma unroll
    for (int i = 0; i < 2; i++) {
        int b = b0 + i;
        g_h0[0][b][ug] = 0.f;
        g_c0[b][ug]    = 0.f;
        g_h1[0][b][ug] = 0.f;
        g_c1[b][ug]    = 0.f;
    }
    grid_barrier();

    for (int t = 0; t <= TT; t++) {
        if (t < TT) {
            // layer0 step t: A = [x_t (128) | h0_prev (256)], K=384
            const float* h0in = &g_h0[t & 1][0][0];
            float* h0out = &g_h0[(t & 1) ^ 1][0][0];
            lstm_phase(&sm,
                       x + (long)t * II, (long)TT * II, II,
                       h0in,
                       Wih0, II, Whh0,
                       &g_c0[0][0], h0out,
                       bias0, II + HH,
                       tid, bt, ut, u, bq, b0, ug);
        }
        if (t > 0) {
            // layer1 step s=t-1: A = [h0[s] (256) | h1_prev (256)], K=512
            const float* in0 = &g_h0[t & 1][0][0];     // layer0 output of step s
            const float* h1in = &g_h1[(t - 1) & 1][0][0];
            float* h1out = &g_h1[t & 1][0][0];
            lstm_phase(&sm,
                       in0, HH, HH,
                       h1in,
                       Wih1, HH, Whh1,
                       &g_c1[0][0], h1out,
                       bias1, HH + HH,
                       tid, bt, ut, u, bq, b0, ug);
        }
        grid_barrier();
    }
    // final h1 (after step 511) lives in g_h1[(512)&1] = g_h1[0]
}

// out[b][c] = dot(h1_final[b], fcW[c]) + fcb[c]
__global__ void classifier_kernel(const float* __restrict__ fcW,
                                  const float* __restrict__ fcb,
                                  float* __restrict__ out)
{
    __shared__ float hs[HH];
    int b = blockIdx.x;
    for (int i = threadIdx.x; i < HH; i += blockDim.x)
        hs[i] = g_h1[0][b][i];
    __syncthreads();

    int warp = threadIdx.x >> 5;
    int lane = threadIdx.x & 31;
    for (int c = warp; c < CC; c += 8) {
        float sum = 0.f;
        const float* wrow = fcW + (long)c * HH;
#pragma unroll
        for (int k = lane; k < HH; k += 32)
            sum += hs[k] * wrow[k];
#pragma unroll
        for (int off = 16; off; off >>= 1)
            sum += __shfl_xor_sync(0xffffffffu, sum, off);
        if (lane == 0)
            out[(long)b * CC + c] = sum + fcb[c];
    }
}

extern "C" void kernel_launch(void* const* d_in, const int* in_sizes, int n_in,
                              void* d_out, int out_size)
{
    const float* x    = (const float*)d_in[0];
    const float* Wih0 = (const float*)d_in[1];
    const float* Whh0 = (const float*)d_in[2];
    const float* bih0 = (const float*)d_in[3];
    const float* bhh0 = (const float*)d_in[4];
    const float* Wih1 = (const float*)d_in[5];
    const float* Whh1 = (const float*)d_in[6];
    const float* bih1 = (const float*)d_in[7];
    const float* bhh1 = (const float*)d_in[8];
    const float* fcW  = (const float*)d_in[9];
    const float* fcb  = (const float*)d_in[10];
    float* out = (float*)d_out;

    lstm_persistent<<<NCTA, NTHREADS>>>(x, Wih0, Whh0, bih0, bhh0,
                                        Wih1, Whh1, bih1, bhh1);
    classifier_kernel<<<BB, 256>>>(fcW, fcb, out);
}

// round 4
// speedup vs baseline: 1.1970x; 1.0009x over previous
#include <cuda_runtime.h>
#include <math.h>

#define BB 256   // batch
#define TT 512   // timesteps
#define II 128   // input dim
#define HH 256   // hidden dim
#define CC 1000  // classes

#define NCTA 128
#define NTHREADS 256
#define KC 32

// Persistent state (double-buffered h per layer; c updated in place)
__device__ float g_h0[2][BB][HH];
__device__ float g_c0[BB][HH];
__device__ float g_h1[2][BB][HH];
__device__ float g_c1[BB][HH];

// Grid barrier state
__device__ unsigned int g_bar_count = 0;
__device__ unsigned int g_bar_gen = 0;

__device__ __forceinline__ float sigmoidf_(float x) {
    return 1.0f / (1.0f + __expf(-x));
}

__device__ __forceinline__ void grid_barrier() {
    __syncthreads();
    if (threadIdx.x == 0) {
        __threadfence();
        unsigned int gen = g_bar_gen;
        unsigned int t = atomicAdd(&g_bar_count, 1u);
        if (t == NCTA - 1) {
            g_bar_count = 0;
            __threadfence();
            atomicExch(&g_bar_gen, gen + 1);
        } else {
            volatile unsigned int* p = &g_bar_gen;
            while (*p == gen) { __nanosleep(64); }
        }
        __threadfence();
    }
    __syncthreads();
}

struct Smem {
    float As[2][KC * 34];   // transposed [k][b_local], pad row to 34 floats
    float Ws[2][KC * 64];   // transposed [k][slot], slot=u*4+g, XOR-swizzled
};

// One GEMM+activation phase: out tile = 32 batches x 16 units (64 gate rows).
// A = concat(seg0[K0], seg1[HH]); W = concat(W0 rows len w0len, W1 rows len HH).
__device__ __forceinline__ void lstm_phase(
    Smem* sm,
    const float* __restrict__ A0, long a0str, int K0,
    const float* __restrict__ A1,
    const float* __restrict__ W0, int w0len,
    const float* __restrict__ W1,
    float* __restrict__ cbuf, float* __restrict__ hout,
    const float* bias,      // 4 per-thread gate biases (registers)
    int KTOT,
    int tid, int bt, int ut, int u, int bq, int b0, int ug)
{
    // staging-role indices
    const int a_b   = bt * 32 + (tid >> 3);  // global batch this thread stages
    const int s_b   = tid >> 3;              // local batch 0..31
    const int a_k4  = tid & 7;               // A f4 index within chunk
    const int slot  = tid >> 2;              // local W slot 0..63 (= u*4+g)
    const int su    = slot >> 2;
    const int sg    = slot & 3;
    const int srow  = sg * HH + ut * 16 + su; // global weight row
    const int f0    = (tid & 3) * 2;          // W f4 pair base 0..7

    float4 va, wa, wb;
    // prologue: load chunk 0 into registers
    {
        int k = a_k4 * 4;
        const float* src = (k < K0) ? (A0 + (long)a_b * a0str + k)
                                    : (A1 + (long)a_b * HH + (k - K0));
        va = __ldcg((const float4*)src);
        int kw = f0 * 4;
        const float* wsrc = (kw < K0) ? (W0 + (long)srow * w0len + kw)
                                      : (W1 + (long)srow * HH + (kw - K0));
        wa = *(const float4*)wsrc;
        wb = *(const float4*)(wsrc + 4);
    }

    float acc[2][4];
#pragma unroll
    for (int i = 0; i < 2; i++)
#pragma unroll
        for (int g = 0; g < 4; g++) acc[i][g] = 0.f;

    const int nch = KTOT / KC;
    int p = 0;
    for (int c = 0; c < nch; c++) {
        float* Asp = sm->As[p];
        float* Wsp = sm->Ws[p];
        // store staged chunk (transposed; W XOR-swizzled by k's f4 index)
#pragma unroll
        for (int j = 0; j < 4; j++)
            Asp[(a_k4 * 4 + j) * 34 + s_b] = ((float*)&va)[j];
#pragma unroll
        for (int j = 0; j < 4; j++) {
            int k = f0 * 4 + j;
            Wsp[(k * 16 + (su ^ f0)) * 4 + sg] = ((float*)&wa)[j];
        }
#pragma unroll
        for (int j = 0; j < 4; j++) {
            int k = (f0 + 1) * 4 + j;
            Wsp[(k * 16 + (su ^ (f0 + 1))) * 4 + sg] = ((float*)&wb)[j];
        }
        __syncthreads();
        // prefetch chunk c+1 into registers (hidden under compute)
        if (c + 1 < nch) {
            int kb = (c + 1) * KC;
            int k = kb + a_k4 * 4;
            const float* src = (k < K0) ? (A0 + (long)a_b * a0str + k)
                                        : (A1 + (long)a_b * HH + (k - K0));
            va = __ldcg((const float4*)src);
            int kw = kb + f0 * 4;
            const float* wsrc = (kw < K0) ? (W0 + (long)srow * w0len + kw)
                                          : (W1 + (long)srow * HH + (kw - K0));
            wa = *(const float4*)wsrc;
            wb = *(const float4*)(wsrc + 4);
        }
        // compute chunk
#pragma unroll
        for (int k = 0; k < KC; k++) {
            float2 a2 = *(const float2*)&Asp[k * 34 + bq * 2];
            float4 w4 = *(const float4*)&Wsp[(k * 16 + (u ^ (k >> 2))) * 4];
            acc[0][0] = fmaf(w4.x, a2.x, acc[0][0]);
            acc[0][1] = fmaf(w4.y, a2.x, acc[0][1]);
            acc[0][2] = fmaf(w4.z, a2.x, acc[0][2]);
            acc[0][3] = fmaf(w4.w, a2.x, acc[0][3]);
            acc[1][0] = fmaf(w4.x, a2.y, acc[1][0]);
            acc[1][1] = fmaf(w4.y, a2.y, acc[1][1]);
            acc[1][2] = fmaf(w4.z, a2.y, acc[1][2]);
            acc[1][3] = fmaf(w4.w, a2.y, acc[1][3]);
        }
        p ^= 1;
    }

    // epilogue: activations + state update (thread owns 2 batches x 1 unit)
#pragma unroll
    for (int i = 0; i < 2; i++) {
        long off = (long)(b0 + i) * HH + ug;
        float ig = sigmoidf_(acc[i][0] + bias[0]);
        float fg = sigmoidf_(acc[i][1] + bias[1]);
        float gg = tanhf(acc[i][2] + bias[2]);
        float og = sigmoidf_(acc[i][3] + bias[3]);
        float cn = fg * cbuf[off] + ig * gg;
        cbuf[off] = cn;
        hout[off] = og * tanhf(cn);
    }
}

__global__ __launch_bounds__(NTHREADS, 1) void lstm_persistent(
    const float* __restrict__ x,
    const float* __restrict__ Wih0, const float* __restrict__ Whh0,
    const float* __restrict__ bih0, const float* __restrict__ bhh0,
    const float* __restrict__ Wih1, const float* __restrict__ Whh1,
    const float* __restrict__ bih1, const float* __restrict__ bhh1)
{
    __shared__ Smem sm;

    const int tid = threadIdx.x;
    const int cid = blockIdx.x;
    const int bt = cid >> 4;     // batch tile (32 batches)
    const int ut = cid & 15;     // unit tile (16 units)

    // compute-role indices
    const int u  = tid & 15;             // unit within tile
    const int bq = tid >> 4;             // 0..15 -> batches 2bq, 2bq+1
    const int b0 = bt * 32 + bq * 2;
    const int ug = ut * 16 + u;          // global hidden unit

    // biases held in registers for all 512 steps
    float bias0[4], bias1[4];
#pragma unroll
    for (int g = 0; g < 4; g++) {
        bias0[g] = bih0[g * HH + ug] + bhh0[g * HH + ug];
        bias1[g] = bih1[g * HH + ug] + bhh1[g * HH + ug];
    }

    // zero owned state (each (b, unit) owned by exactly one thread grid-wide)
#pragma unroll
    for (int i = 0; i < 2; i++) {
        int b = b0 + i;
        g_h0[0][b][ug] = 0.f;
        g_c0[b][ug]    = 0.f;
        g_h1[0][b][ug] = 0.f;
        g_c1[b][ug]    = 0.f;
    }
    grid_barrier();

    for (int t = 0; t <= TT; t++) {
        if (t < TT) {
            // layer0 step t: A = [x_t (128) | h0_prev (256)], K=384
            const float* h0in = &g_h0[t & 1][0][0];
            float* h0out = &g_h0[(t & 1) ^ 1][0][0];
            lstm_phase(&sm,
                       x + (long)t * II, (long)TT * II, II,
                       h0in,
                       Wih0, II, Whh0,
                       &g_c0[0][0], h0out,
                       bias0, II + HH,
                       tid, bt, ut, u, bq, b0, ug);
        }
        if (t > 0) {
            // layer1 step s=t-1: A = [h0[s] (256) | h1_prev (256)], K=512
            const float* in0 = &g_h0[t & 1][0][0];     // layer0 output of step s
            const float* h1in = &g_h1[(t - 1) & 1][0][0];
            float* h1out = &g_h1[t & 1][0][0];
            lstm_phase(&sm,
                       in0, HH, HH,
                       h1in,
                       Wih1, HH, Whh1,
                       &g_c1[0][0], h1out,
                       bias1, HH + HH,
                       tid, bt, ut, u, bq, b0, ug);
        }
        grid_barrier();
    }
    // final h1 (after step 511) lives in g_h1[(512)&1] = g_h1[0]
}

// out[b][c] = dot(h1_final[b], fcW[c]) + fcb[c]
__global__ void classifier_kernel(const float* __restrict__ fcW,
                                  const float* __restrict__ fcb,
                                  float* __restrict__ out)
{
    __shared__ float hs[HH];
    int b = blockIdx.x;
    for (int i = threadIdx.x; i < HH; i += blockDim.x)
        hs[i] = g_h1[0][b][i];
    __syncthreads();

    int warp = threadIdx.x >> 5;
    int lane = threadIdx.x & 31;
    for (int c = warp; c < CC; c += 8) {
        float sum = 0.f;
        const float* wrow = fcW + (long)c * HH;
#pragma unroll
        for (int k = lane; k < HH; k += 32)
            sum += hs[k] * wrow[k];
#pragma unroll
        for (int off = 16; off; off >>= 1)
            sum += __shfl_xor_sync(0xffffffffu, sum, off);
        if (lane == 0)
            out[(long)b * CC + c] = sum + fcb[c];
    }
}

extern "C" void kernel_launch(void* const* d_in, const int* in_sizes, int n_in,
                              void* d_out, int out_size)
{
    const float* x    = (const float*)d_in[0];
    const float* Wih0 = (const float*)d_in[1];
    const float* Whh0 = (const float*)d_in[2];
    const float* bih0 = (const float*)d_in[3];
    const float* bhh0 = (const float*)d_in[4];
    const float* Wih1 = (const float*)d_in[5];
    const float* Whh1 = (const float*)d_in[6];
    const float* bih1 = (const float*)d_in[7];
    const float* bhh1 = (const float*)d_in[8];
    const float* fcW  = (const float*)d_in[9];
    const float* fcb  = (const float*)d_in[10];
    float* out = (float*)d_out;

    lstm_persistent<<<NCTA, NTHREADS>>>(x, Wih0, Whh0, bih0, bhh0,
                                        Wih1, Whh1, bih1, bhh1);
    classifier_kernel<<<BB, 256>>>(fcW, fcb, out);
}

// round 6
// speedup vs baseline: 3.0118x; 2.5162x over previous
#include <cuda_runtime.h>
#include <math.h>
#include <cstdint>

#define BB 256
#define TT 512
#define II 128
#define HH 256
#define CC 1000

#define NCTA 128     // 64 per layer
#define NTH  256
#define KCH  64      // K per chunk (8 ksteps of k8)

// smem: A double buffer 2*64*68*4 = 34816 ; Bpk up to 64ks*8nt*32lane*2*4 = 131072
#define ABYTES 17408
#define BPK_OFF 34816
#define SMEM_BYTES (34816 + 131072)

__device__ float g_h0[2][BB][HH];
__device__ float g_h1[2][BB][HH];
__device__ unsigned int g_bar_count = 0;
__device__ unsigned int g_bar_gen = 0;

__device__ __forceinline__ float sigm_(float x) { return __fdividef(1.f, 1.f + __expf(-x)); }
__device__ __forceinline__ float tanh_(float x) { return 1.f - __fdividef(2.f, __expf(2.f * x) + 1.f); }

__device__ __forceinline__ uint32_t rna_tf32(float v) {
    uint32_t r;
    asm("cvt.rna.tf32.f32 %0, %1;" : "=r"(r) : "f"(v));
    return r;
}

__device__ __forceinline__ void grid_barrier() {
    __syncthreads();
    if (threadIdx.x == 0) {
        __threadfence();
        unsigned int gen = g_bar_gen;
        unsigned int t = atomicAdd(&g_bar_count, 1u);
        if (t == NCTA - 1) {
            g_bar_count = 0;
            __threadfence();
            atomicExch(&g_bar_gen, gen + 1);
        } else {
            volatile unsigned int* p = &g_bar_gen;
            while (*p == gen) { __nanosleep(64); }
        }
        __threadfence();
    }
    __syncthreads();
}

#define CP_COMMIT() asm volatile("cp.async.commit_group;" ::: "memory")
#define CP_WAIT1()  asm volatile("cp.async.wait_group 1;" ::: "memory")

// stage one A chunk (64 rows x 64 k) into buffer c&1
__device__ __forceinline__ void issue_chunk(
    char* smem, int c, int K0,
    const float* __restrict__ seg0, long rs0,
    const float* __restrict__ seg1,
    int mt, int tid)
{
    char* dst = smem + ((c & 1) ? ABYTES : 0);
#pragma unroll
    for (int i = 0; i < 4; i++) {
        int idx = tid + i * NTH;          // 0..1023
        int r = idx >> 4;                 // row 0..63
        int sg = idx & 15;                // 16B segment
        int kb = c * KCH + sg * 4;
        const float* g;
        if (kb < K0) g = seg0 + (long)(mt * 64 + r) * rs0 + kb;
        else         g = seg1 + (long)(mt * 64 + r) * HH + (kb - K0);
        uint32_t sa;
        asm("{ .reg .u64 t; cvta.to.shared.u64 t, %1; cvt.u32.u64 %0, t; }"
            : "=r"(sa) : "l"(dst + r * 272 + sg * 16));
        asm volatile("cp.async.cg.shared.global [%0], [%1], 16;" :: "r"(sa), "l"(g) : "memory");
    }
}

__global__ __launch_bounds__(NTH, 1) void lstm_mma(
    const float* __restrict__ x,
    const float* __restrict__ Wih0, const float* __restrict__ Whh0,
    const float* __restrict__ bih0, const float* __restrict__ bhh0,
    const float* __restrict__ Wih1, const float* __restrict__ Whh1,
    const float* __restrict__ bih1, const float* __restrict__ bhh1)
{
    extern __shared__ char smem[];
    const int tid = threadIdx.x;
    const int cid = blockIdx.x;
    const int layer = cid >> 6;
    const int lb = cid & 63;
    const int mt = lb >> 4;       // batch tile (64 rows)
    const int nt = lb & 15;       // unit tile (16 units)

    const int K0   = layer ? HH : II;
    const int Ktot = layer ? (HH + HH) : (II + HH);
    const int nch  = Ktot / KCH;
    const int nks  = Ktot / 8;

    const float* WA = layer ? Wih1 : Wih0;
    const float* WB = layer ? Whh1 : Whh0;
    const float* bA = layer ? bih1 : bih0;
    const float* bB = layer ? bhh1 : bhh0;

    // warp roles
    const int w    = tid >> 5;
    const int lane = tid & 31;
    const int ms   = w & 3;       // M slice (16 rows)
    const int nh   = w >> 2;      // N half (32 cols = 4 ntiles)
    const int g    = lane >> 2;
    const int tg   = lane & 3;

    // ---- pack weights into B-fragment layout: Bpk[ks][nt_idx][lane][2] ----
    uint32_t* Bpk = (uint32_t*)(smem + BPK_OFF);
    for (int idx = tid; idx < nks * 512; idx += NTH) {
        int j   = idx & 1;
        int ln  = (idx >> 1) & 31;
        int nti = (idx >> 6) & 7;
        int ks  = idx >> 9;
        int lg  = ln >> 2, ltg = ln & 3;
        int k   = ks * 8 + ltg + 4 * j;
        int s   = 8 * nti + lg;                 // slot within CTA's 64 cols
        int row = (s & 3) * HH + nt * 16 + (s >> 2);
        float v = (k < K0) ? WA[(size_t)row * K0 + k]
                           : WB[(size_t)row * HH + (k - K0)];
        Bpk[idx] = rna_tf32(v);
    }

    // ---- biases into registers: 4 ntiles x 4 gates ----
    float biasr[4][4];
#pragma unroll
    for (int ntl = 0; ntl < 4; ntl++) {
        int ugl = nt * 16 + 8 * nh + 2 * ntl + (tg >> 1);
#pragma unroll
        for (int gt = 0; gt < 4; gt++)
            biasr[ntl][gt] = bA[gt * HH + ugl] + bB[gt * HH + ugl];
    }

    // ---- zero initial h (grid-cooperative) ----
    {
        float* p0 = &g_h0[0][0][0];
        float* p1 = &g_h1[0][0][0];
        for (int i = cid * NTH + tid; i < BB * HH; i += NCTA * NTH) { p0[i] = 0.f; p1[i] = 0.f; }
    }
    __syncthreads();
    grid_barrier();

    float cst[4];
#pragma unroll
    for (int q = 0; q < 4; q++) cst[q] = 0.f;

    for (int t = 0; t <= TT; t++) {
        const bool active = layer ? (t > 0) : (t < TT);
        if (active) {
            const int s = layer ? (t - 1) : t;
            const float* seg0; long rs0; const float* seg1; float* hout;
            if (layer == 0) {
                seg0 = x + (size_t)s * II;  rs0 = (long)TT * II;
                seg1 = &g_h0[s & 1][0][0];
                hout = &g_h0[(s & 1) ^ 1][0][0];
            } else {
                seg0 = &g_h0[t & 1][0][0];  rs0 = HH;
                seg1 = &g_h1[s & 1][0][0];
                hout = &g_h1[t & 1][0][0];
            }

            float acc[4][4];
#pragma unroll
            for (int q = 0; q < 4; q++)
#pragma unroll
                for (int i = 0; i < 4; i++) acc[q][i] = 0.f;

            issue_chunk(smem, 0, K0, seg0, rs0, seg1, mt, tid);
            CP_COMMIT();

            for (int c = 0; c < nch; c++) {
                if (c + 1 < nch) issue_chunk(smem, c + 1, K0, seg0, rs0, seg1, mt, tid);
                CP_COMMIT();
                CP_WAIT1();
                __syncthreads();

                const uint32_t* Ab = (const uint32_t*)(smem + ((c & 1) ? ABYTES : 0));
                const int ra = (ms * 16 + g) * 68;
#pragma unroll
                for (int ks = 0; ks < 8; ks++) {
                    const int kk = ks * 8 + tg;
                    uint32_t a0 = Ab[ra + kk];
                    uint32_t a1 = Ab[ra + 8 * 68 + kk];
                    uint32_t a2 = Ab[ra + kk + 4];
                    uint32_t a3 = Ab[ra + 8 * 68 + kk + 4];
                    const int ksg = c * 8 + ks;
#pragma unroll
                    for (int ntl = 0; ntl < 4; ntl++) {
                        const uint32_t* bp = Bpk + ((ksg * 8 + nh * 4 + ntl) * 32 + lane) * 2;
                        uint32_t b0 = bp[0], b1 = bp[1];
                        asm volatile(
                            "mma.sync.aligned.m16n8k8.row.col.f32.tf32.tf32.f32 "
                            "{%0,%1,%2,%3}, {%4,%5,%6,%7}, {%8,%9}, {%0,%1,%2,%3};"
                            : "+f"(acc[ntl][0]), "+f"(acc[ntl][1]),
                              "+f"(acc[ntl][2]), "+f"(acc[ntl][3])
                            : "r"(a0), "r"(a1), "r"(a2), "r"(a3), "r"(b0), "r"(b1));
                    }
                }
                __syncthreads();
            }

            // epilogue: quad-exchange gates, activations, state update
            const bool even = !(tg & 1);
            const int rl = ms * 16 + g + (even ? 0 : 8);
            const int rowg = mt * 64 + rl;
#pragma unroll
            for (int ntl = 0; ntl < 4; ntl++) {
                float e0 = __shfl_xor_sync(0xffffffffu, acc[ntl][0], 1);
                float e1 = __shfl_xor_sync(0xffffffffu, acc[ntl][1], 1);
                float e2 = __shfl_xor_sync(0xffffffffu, acc[ntl][2], 1);
                float e3 = __shfl_xor_sync(0xffffffffu, acc[ntl][3], 1);
                float pi = (even ? acc[ntl][0] : e2) + biasr[ntl][0];
                float pf = (even ? acc[ntl][1] : e3) + biasr[ntl][1];
                float pg = (even ? e0 : acc[ntl][2]) + biasr[ntl][2];
                float po = (even ? e1 : acc[ntl][3]) + biasr[ntl][3];
                float cn = sigm_(pf) * cst[ntl] + sigm_(pi) * tanh_(pg);
                cst[ntl] = cn;
                float hv = sigm_(po) * tanh_(cn);
                int ug = nt * 16 + 8 * nh + 2 * ntl + (tg >> 1);
                hout[(size_t)rowg * HH + ug] = __uint_as_float(rna_tf32(hv));
            }
        }
        grid_barrier();
    }
}

__global__ void classifier_kernel(const float* __restrict__ fcW,
                                  const float* __restrict__ fcb,
                                  float* __restrict__ out)
{
    __shared__ float hs[HH];
    int b = blockIdx.x;
    for (int i = threadIdx.x; i < HH; i += blockDim.x)
        hs[i] = g_h1[0][b][i];
    __syncthreads();
    int warp = threadIdx.x >> 5, lane = threadIdx.x & 31;
    for (int c = warp; c < CC; c += 8) {
        float sum = 0.f;
        const float* wrow = fcW + (size_t)c * HH;
#pragma unroll
        for (int k = lane; k < HH; k += 32) sum += hs[k] * wrow[k];
#pragma unroll
        for (int off = 16; off; off >>= 1) sum += __shfl_xor_sync(0xffffffffu, sum, off);
        if (lane == 0) out[(size_t)b * CC + c] = sum + fcb[c];
    }
}

extern "C" void kernel_launch(void* const* d_in, const int* in_sizes, int n_in,
                              void* d_out, int out_size)
{
    const float* x    = (const float*)d_in[0];
    const float* Wih0 = (const float*)d_in[1];
    const float* Whh0 = (const float*)d_in[2];
    const float* bih0 = (const float*)d_in[3];
    const float* bhh0 = (const float*)d_in[4];
    const float* Wih1 = (const float*)d_in[5];
    const float* Whh1 = (const float*)d_in[6];
    const float* bih1 = (const float*)d_in[7];
    const float* bhh1 = (const float*)d_in[8];
    const float* fcW  = (const float*)d_in[9];
    const float* fcb  = (const float*)d_in[10];
    float* out = (float*)d_out;

    cudaFuncSetAttribute(lstm_mma, cudaFuncAttributeMaxDynamicSharedMemorySize, SMEM_BYTES);
    lstm_mma<<<NCTA, NTH, SMEM_BYTES>>>(x, Wih0, Whh0, bih0, bhh0,
                                        Wih1, Whh1, bih1, bhh1);
    classifier_kernel<<<BB, 256>>>(fcW, fcb, out);
}

// round 7
// speedup vs baseline: 6.3101x; 2.0951x over previous
#include <cuda_runtime.h>
#include <cuda_fp16.h>
#include <math.h>
#include <cstdint>

#define BB 256
#define TT 512
#define II 128
#define HH 256
#define CC 1000

#define NCTA 128     // 64 per layer; barrier groups of 32 by batch tile
#define NTH  256
#define KCH  128     // K halves per chunk (8 k16 steps)
#define NBUF 3

#define APITCH 272                   // bytes per A row (128 halves + 8 pad)
#define ABUF  (64 * APITCH)          // 17408 B per A buffer
#define BPK_OFF (NBUF * ABUF)        // 52224
#define SMEM_BYTES (BPK_OFF + 65536) // + max Bpk (layer1: 32 ks * 2KB)

__device__ __half g_xh[BB * TT * II];
__device__ __half g_h0[2][BB][HH];
__device__ __half g_h1[2][BB][HH];
__device__ unsigned int g_bcnt[4] = {0, 0, 0, 0};
__device__ unsigned int g_bgen[4] = {0, 0, 0, 0};

__device__ __forceinline__ float sigm_(float x) { return __fdividef(1.f, 1.f + __expf(-x)); }
__device__ __forceinline__ float tanh_(float x) { return 1.f - __fdividef(2.f, __expf(2.f * x) + 1.f); }

__device__ __forceinline__ uint32_t smem_u32(const void* p) {
    uint32_t a;
    asm("{ .reg .u64 t; cvta.to.shared.u64 t, %1; cvt.u32.u64 %0, t; }" : "=r"(a) : "l"(p));
    return a;
}

__device__ __forceinline__ void group_barrier(int grp) {
    __syncthreads();
    if (threadIdx.x == 0) {
        __threadfence();
        unsigned int gen = g_bgen[grp];
        unsigned int t = atomicAdd(&g_bcnt[grp], 1u);
        if (t == 31u) {
            g_bcnt[grp] = 0;
            __threadfence();
            atomicExch(&g_bgen[grp], gen + 1);
        } else {
            volatile unsigned int* p = &g_bgen[grp];
            while (*p == gen) { __nanosleep(32); }
        }
        __threadfence();
    }
    __syncthreads();
}

#define CP_COMMIT() asm volatile("cp.async.commit_group;" ::: "memory")
#define CP_WAIT1()  asm volatile("cp.async.wait_group 1;" ::: "memory")

// stage one A chunk (64 rows x 128 halves) into ring buffer c%3
__device__ __forceinline__ void issue_chunk(
    uint32_t abase, int c, int K0,
    const __half* __restrict__ seg0, long rs0,
    const __half* __restrict__ seg1,
    int mt, int tid, int nch)
{
    if (c >= nch) { CP_COMMIT(); return; }
    const __half* base; long rs; int koff;
    if (c * KCH < K0) { base = seg0; rs = rs0; koff = c * KCH; }
    else              { base = seg1; rs = HH;  koff = c * KCH - K0; }
    uint32_t dst = abase + (uint32_t)(c % NBUF) * ABUF;
#pragma unroll
    for (int i = 0; i < 4; i++) {
        int idx = tid + i * NTH;      // 0..1023
        int r  = idx >> 4;            // row 0..63
        int sg = idx & 15;            // 16B segment (8 halves)
        const __half* g = base + (long)(mt * 64 + r) * rs + koff + sg * 8;
        uint32_t sa = dst + (uint32_t)(r * APITCH + sg * 16);
        asm volatile("cp.async.cg.shared.global [%0], [%1], 16;" :: "r"(sa), "l"(g) : "memory");
    }
    CP_COMMIT();
}

__global__ __launch_bounds__(NTH, 1) void lstm_mma(
    const float* __restrict__ Wih0, const float* __restrict__ Whh0,
    const float* __restrict__ bih0, const float* __restrict__ bhh0,
    const float* __restrict__ Wih1, const float* __restrict__ Whh1,
    const float* __restrict__ bih1, const float* __restrict__ bhh1)
{
    extern __shared__ char smem[];
    const uint32_t smb = smem_u32(smem);
    const int tid = threadIdx.x;
    const int cid = blockIdx.x;
    const int layer = cid >> 6;
    const int lb = cid & 63;
    const int mt = lb >> 4;       // batch tile (64 rows) == barrier group
    const int nt = lb & 15;       // unit tile (16 units)

    const int K0   = layer ? HH : II;
    const int Ktot = layer ? (HH + HH) : (II + HH);
    const int nch  = Ktot / KCH;           // 3 or 4
    const int nks  = Ktot / 16;            // 24 or 32

    const float* WA = layer ? Wih1 : Wih0;
    const float* WB = layer ? Whh1 : Whh0;
    const float* bA = layer ? bih1 : bih0;
    const float* bB = layer ? bhh1 : bhh0;

    const int w    = tid >> 5;
    const int lane = tid & 31;
    const int ms   = w & 3;       // M slice (16 rows)
    const int nh   = w >> 2;      // N half (4 ntiles)
    const int g    = lane >> 2;
    const int tg   = lane & 3;

    // ---- pack fp16 weights into B-fragment layout Bpk[ks][nti][lane][2] ----
    uint32_t* Bpk = (uint32_t*)(smem + BPK_OFF);
    for (int idx = tid; idx < nks * 512; idx += NTH) {
        int j   = idx & 1;
        int ln  = (idx >> 1) & 31;
        int nti = (idx >> 6) & 7;
        int ks  = idx >> 9;
        int lg  = ln >> 2, ltg = ln & 3;
        int k   = ks * 16 + j * 8 + ltg * 2;
        int s   = 8 * nti + lg;
        int row = (s & 3) * HH + nt * 16 + (s >> 2);
        float w0, w1;
        if (k < K0) { w0 = WA[(size_t)row * K0 + k];           w1 = WA[(size_t)row * K0 + k + 1]; }
        else        { w0 = WB[(size_t)row * HH + (k - K0)];    w1 = WB[(size_t)row * HH + (k - K0) + 1]; }
        __half2 hw = __floats2half2_rn(w0, w1);
        Bpk[idx] = *(uint32_t*)&hw;
    }

    // ---- biases: 4 ntiles x 4 gates ----
    float biasr[4][4];
#pragma unroll
    for (int ntl = 0; ntl < 4; ntl++) {
        int ugl = nt * 16 + 8 * nh + 2 * ntl + (tg >> 1);
#pragma unroll
        for (int gt = 0; gt < 4; gt++)
            biasr[ntl][gt] = bA[gt * HH + ugl] + bB[gt * HH + ugl];
    }

    // ---- group-local zero-init of h (rows mt*64..mt*64+63, all 4 buffers) ----
    {
        const int mrank = layer * 16 + nt;
        const int gt = mrank * NTH + tid;        // 0..8191 within group
        uint32_t* bufs[4] = {
            (uint32_t*)&g_h0[0][mt * 64][0], (uint32_t*)&g_h0[1][mt * 64][0],
            (uint32_t*)&g_h1[0][mt * 64][0], (uint32_t*)&g_h1[1][mt * 64][0]
        };
        for (int i = gt; i < 4 * 8192; i += 32 * NTH)
            bufs[i >> 13][i & 8191] = 0u;
    }
    group_barrier(mt);

    // ldmatrix per-lane row offset within an A buffer
    const int lrow = ms * 16 + (lane & 7) + ((lane >> 3) & 1) * 8;
    const uint32_t rowoff = (uint32_t)(lrow * APITCH + ((lane >> 4) & 1) * 16);

    float cst[4];
#pragma unroll
    for (int q = 0; q < 4; q++) cst[q] = 0.f;

    for (int t = 0; t <= TT; t++) {
        const bool active = layer ? (t > 0) : (t < TT);
        if (active) {
            const int s = layer ? (t - 1) : t;
            const __half* seg0; long rs0; const __half* seg1; __half* hout;
            if (layer == 0) {
                seg0 = g_xh + (size_t)s * II;  rs0 = (long)TT * II;
                seg1 = &g_h0[s & 1][0][0];
                hout = &g_h0[(s & 1) ^ 1][0][0];
            } else {
                seg0 = &g_h0[t & 1][0][0];     rs0 = HH;
                seg1 = &g_h1[s & 1][0][0];
                hout = &g_h1[t & 1][0][0];
            }

            float acc[4][4];
#pragma unroll
            for (int q = 0; q < 4; q++)
#pragma unroll
                for (int i = 0; i < 4; i++) acc[q][i] = 0.f;

            issue_chunk(smb, 0, K0, seg0, rs0, seg1, mt, tid, nch);
            issue_chunk(smb, 1, K0, seg0, rs0, seg1, mt, tid, nch);

            for (int c = 0; c < nch; c++) {
                CP_WAIT1();
                __syncthreads();
                issue_chunk(smb, c + 2, K0, seg0, rs0, seg1, mt, tid, nch);

                const uint32_t ab = smb + (uint32_t)(c % NBUF) * ABUF + rowoff;
#pragma unroll
                for (int ks = 0; ks < 8; ks++) {
                    uint32_t a0, a1, a2, a3;
                    asm volatile(
                        "ldmatrix.sync.aligned.m8n8.x4.shared.b16 {%0,%1,%2,%3}, [%4];"
                        : "=r"(a0), "=r"(a1), "=r"(a2), "=r"(a3)
                        : "r"(ab + (uint32_t)(ks * 32)));
                    const int ksg = c * 8 + ks;
#pragma unroll
                    for (int ntl = 0; ntl < 4; ntl++) {
                        uint2 bv = *(const uint2*)(Bpk + ((ksg * 8 + nh * 4 + ntl) * 32 + lane) * 2);
                        asm volatile(
                            "mma.sync.aligned.m16n8k16.row.col.f32.f16.f16.f32 "
                            "{%0,%1,%2,%3}, {%4,%5,%6,%7}, {%8,%9}, {%0,%1,%2,%3};"
                            : "+f"(acc[ntl][0]), "+f"(acc[ntl][1]),
                              "+f"(acc[ntl][2]), "+f"(acc[ntl][3])
                            : "r"(a0), "r"(a1), "r"(a2), "r"(a3), "r"(bv.x), "r"(bv.y));
                    }
                }
            }

            // epilogue: quad-exchange gates, activations, state update
            const bool even = !(tg & 1);
            const int rl = ms * 16 + g + (even ? 0 : 8);
            const int rowg = mt * 64 + rl;
#pragma unroll
            for (int ntl = 0; ntl < 4; ntl++) {
                float e0 = __shfl_xor_sync(0xffffffffu, acc[ntl][0], 1);
                float e1 = __shfl_xor_sync(0xffffffffu, acc[ntl][1], 1);
                float e2 = __shfl_xor_sync(0xffffffffu, acc[ntl][2], 1);
                float e3 = __shfl_xor_sync(0xffffffffu, acc[ntl][3], 1);
                float pi = (even ? acc[ntl][0] : e2) + biasr[ntl][0];
                float pf = (even ? acc[ntl][1] : e3) + biasr[ntl][1];
                float pg = (even ? e0 : acc[ntl][2]) + biasr[ntl][2];
                float po = (even ? e1 : acc[ntl][3]) + biasr[ntl][3];
                float cn = sigm_(pf) * cst[ntl] + sigm_(pi) * tanh_(pg);
                cst[ntl] = cn;
                float hv = sigm_(po) * tanh_(cn);
                int ug = nt * 16 + 8 * nh + 2 * ntl + (tg >> 1);
                hout[(size_t)rowg * HH + ug] = __float2half_rn(hv);
            }
        }
        group_barrier(mt);
    }
}

__global__ void convert_x(const float* __restrict__ x) {
    const int total = BB * TT * II / 2;
    int idx = blockIdx.x * blockDim.x + threadIdx.x;
    int stride = gridDim.x * blockDim.x;
    __half2* dst = (__half2*)g_xh;
    const float2* src = (const float2*)x;
    for (int i = idx; i < total; i += stride) {
        float2 v = src[i];
        dst[i] = __floats2half2_rn(v.x, v.y);
    }
}

// tiled classifier: out[256,1000] = h1 @ fcW^T + fcb
__global__ __launch_bounds__(256) void classifier2(
    const float* __restrict__ fcW, const float* __restrict__ fcb,
    float* __restrict__ out)
{
    __shared__ float hs[32][68];
    __shared__ float ws[32][68];
    const int bt = blockIdx.x;   // 0..3  (64 batches)
    const int ct = blockIdx.y;   // 0..15 (64 classes)
    const int tid = threadIdx.x;
    const int bq = tid >> 4, cq = tid & 15;
    float acc[4][4];
#pragma unroll
    for (int i = 0; i < 4; i++)
#pragma unroll
        for (int j = 0; j < 4; j++) acc[i][j] = 0.f;

    for (int k0 = 0; k0 < HH; k0 += 32) {
        __syncthreads();
        for (int i = tid; i < 64 * 32; i += 256) {
            int b = i >> 5, k = i & 31;
            hs[k][b] = __half2float(g_h1[0][bt * 64 + b][k0 + k]);
        }
        for (int i = tid; i < 64 * 32; i += 256) {
            int c = i >> 5, k = i & 31;
            int gc = ct * 64 + c;
            ws[k][c] = (gc < CC) ? fcW[(size_t)gc * HH + k0 + k] : 0.f;
        }
        __syncthreads();
#pragma unroll
        for (int k = 0; k < 32; k++) {
            float a[4], wv[4];
#pragma unroll
            for (int i = 0; i < 4; i++) a[i] = hs[k][bq * 4 + i];
#pragma unroll
            for (int j = 0; j < 4; j++) wv[j] = ws[k][cq * 4 + j];
#pragma unroll
            for (int i = 0; i < 4; i++)
#pragma unroll
                for (int j = 0; j < 4; j++)
                    acc[i][j] = fmaf(a[i], wv[j], acc[i][j]);
        }
    }
#pragma unroll
    for (int i = 0; i < 4; i++) {
        int b = bt * 64 + bq * 4 + i;
#pragma unroll
        for (int j = 0; j < 4; j++) {
            int c = ct * 64 + cq * 4 + j;
            if (c < CC) out[(size_t)b * CC + c] = acc[i][j] + fcb[c];
        }
    }
}

extern "C" void kernel_launch(void* const* d_in, const int* in_sizes, int n_in,
                              void* d_out, int out_size)
{
    const float* x    = (const float*)d_in[0];
    const float* Wih0 = (const float*)d_in[1];
    const float* Whh0 = (const float*)d_in[2];
    const float* bih0 = (const float*)d_in[3];
    const float* bhh0 = (const float*)d_in[4];
    const float* Wih1 = (const float*)d_in[5];
    const float* Whh1 = (const float*)d_in[6];
    const float* bih1 = (const float*)d_in[7];
    const float* bhh1 = (const float*)d_in[8];
    const float* fcW  = (const float*)d_in[9];
    const float* fcb  = (const float*)d_in[10];
    float* out = (float*)d_out;

    convert_x<<<4096, 256>>>(x);
    cudaFuncSetAttribute(lstm_mma, cudaFuncAttributeMaxDynamicSharedMemorySize, SMEM_BYTES);
    lstm_mma<<<NCTA, NTH, SMEM_BYTES>>>(Wih0, Whh0, bih0, bhh0,
                                        Wih1, Whh1, bih1, bhh1);
    classifier2<<<dim3(4, 16), 256>>>(fcW, fcb, out);
}

// round 8
// speedup vs baseline: 8.1506x; 1.2917x over previous
#include <cuda_runtime.h>
#include <cuda_fp16.h>
#include <math.h>
#include <cstdint>

#define BB 256
#define TT 512
#define II 128
#define HH 256
#define CC 1000

#define NCTA 128     // 64 per layer; groups of 16+16 by batch tile
#define NTH  256
#define KCH  128     // K halves per chunk (8 k16 steps)
#define NBUF 4

#define APITCH 272                   // bytes per A row (128 halves + 8 pad)
#define ABUF  (64 * APITCH)          // 17408 B per A buffer
#define BPK_OFF (NBUF * ABUF)        // 69632
#define SMEM_BYTES (BPK_OFF + 65536) // + max Bpk (layer1: 32 ks * 2KB)

__device__ __half g_xh[BB * TT * II];
__device__ __half g_h0[4][BB][HH];   // 4-deep ring
__device__ __half g_h1[2][BB][HH];
__device__ unsigned int g_c0a[4];    // layer0 arrivals per batch group
__device__ unsigned int g_c1a[4];    // layer1 arrivals per batch group

__device__ __forceinline__ float sigm_(float x) { return __fdividef(1.f, 1.f + __expf(-x)); }
__device__ __forceinline__ float tanh_(float x) { return 1.f - __fdividef(2.f, __expf(2.f * x) + 1.f); }

__device__ __forceinline__ uint32_t smem_u32(const void* p) {
    uint32_t a;
    asm("{ .reg .u64 t; cvta.to.shared.u64 t, %1; cvt.u32.u64 %0, t; }" : "=r"(a) : "l"(p));
    return a;
}

// block-wide wait until *p >= v (producer uses red.release.gpu)
__device__ __forceinline__ void wait_ge(unsigned int* p, int v) {
    if (v > 0 && threadIdx.x == 0) {
        unsigned int cur;
        do {
            asm volatile("ld.global.acquire.gpu.u32 %0, [%1];" : "=r"(cur) : "l"(p) : "memory");
        } while ((int)cur < v);
    }
    __syncthreads();
}

// block-wide arrival: all prior stores visible, then +1
__device__ __forceinline__ void arrive(unsigned int* p) {
    __threadfence();
    __syncthreads();
    if (threadIdx.x == 0)
        asm volatile("red.release.gpu.global.add.u32 [%0], %1;" :: "l"(p), "r"(1u) : "memory");
}

#define CP_COMMIT() asm volatile("cp.async.commit_group;" ::: "memory")
__device__ __forceinline__ void cp_wait_n(int n) {
    switch (n) {
    case 0: asm volatile("cp.async.wait_group 0;" ::: "memory"); break;
    case 1: asm volatile("cp.async.wait_group 1;" ::: "memory"); break;
    case 2: asm volatile("cp.async.wait_group 2;" ::: "memory"); break;
    default: asm volatile("cp.async.wait_group 3;" ::: "memory"); break;
    }
}

// stage one A chunk (64 rows x 128 halves) into buffer c
__device__ __forceinline__ void issue_chunk(
    uint32_t abase, int c, int K0,
    const __half* __restrict__ seg0, long rs0,
    const __half* __restrict__ seg1,
    int mt, int tid)
{
    const __half* base; long rs; int koff;
    if (c * KCH < K0) { base = seg0; rs = rs0; koff = c * KCH; }
    else              { base = seg1; rs = HH;  koff = c * KCH - K0; }
    uint32_t dst = abase + (uint32_t)(c & (NBUF - 1)) * ABUF;
#pragma unroll
    for (int i = 0; i < 4; i++) {
        int idx = tid + i * NTH;
        int r  = idx >> 4;
        int sg = idx & 15;
        const __half* g = base + (long)(mt * 64 + r) * rs + koff + sg * 8;
        uint32_t sa = dst + (uint32_t)(r * APITCH + sg * 16);
        asm volatile("cp.async.cg.shared.global [%0], [%1], 16;" :: "r"(sa), "l"(g) : "memory");
    }
    CP_COMMIT();
}

struct StepCtx {
    float acc[4][4];
};

__device__ __forceinline__ void compute_chunks(
    StepCtx& cx, uint32_t smb, const uint32_t* Bpk,
    uint32_t rowoff, int nh, int lane, int nch)
{
#pragma unroll
    for (int c = 0; c < 4; c++) {
        if (c >= nch) break;
        cp_wait_n(nch - 1 - c);
        __syncthreads();
        const uint32_t ab = smb + (uint32_t)c * ABUF + rowoff;
#pragma unroll
        for (int ks = 0; ks < 8; ks++) {
            uint32_t a0, a1, a2, a3;
            asm volatile(
                "ldmatrix.sync.aligned.m8n8.x4.shared.b16 {%0,%1,%2,%3}, [%4];"
                : "=r"(a0), "=r"(a1), "=r"(a2), "=r"(a3)
                : "r"(ab + (uint32_t)(ks * 32)));
            const int ksg = c * 8 + ks;
#pragma unroll
            for (int ntl = 0; ntl < 4; ntl++) {
                uint2 bv = *(const uint2*)(Bpk + ((ksg * 8 + nh * 4 + ntl) * 32 + lane) * 2);
                asm volatile(
                    "mma.sync.aligned.m16n8k16.row.col.f32.f16.f16.f32 "
                    "{%0,%1,%2,%3}, {%4,%5,%6,%7}, {%8,%9}, {%0,%1,%2,%3};"
                    : "+f"(cx.acc[ntl][0]), "+f"(cx.acc[ntl][1]),
                      "+f"(cx.acc[ntl][2]), "+f"(cx.acc[ntl][3])
                    : "r"(a0), "r"(a1), "r"(a2), "r"(a3), "r"(bv.x), "r"(bv.y));
            }
        }
    }
}

__global__ __launch_bounds__(NTH, 1) void lstm_mma(
    const float* __restrict__ Wih0, const float* __restrict__ Whh0,
    const float* __restrict__ bih0, const float* __restrict__ bhh0,
    const float* __restrict__ Wih1, const float* __restrict__ Whh1,
    const float* __restrict__ bih1, const float* __restrict__ bhh1)
{
    extern __shared__ char smem[];
    const uint32_t smb = smem_u32(smem);
    const int tid = threadIdx.x;
    const int cid = blockIdx.x;
    const int layer = cid >> 6;
    const int lb = cid & 63;
    const int mt = lb >> 4;       // batch tile (64 rows) == group
    const int nt = lb & 15;       // unit tile (16 units)

    const int K0   = layer ? HH : II;
    const int nch  = layer ? 4 : 3;
    const int nks  = layer ? 32 : 24;

    const float* WA = layer ? Wih1 : Wih0;
    const float* WB = layer ? Whh1 : Whh0;
    const float* bA = layer ? bih1 : bih0;
    const float* bB = layer ? bhh1 : bhh0;

    const int w    = tid >> 5;
    const int lane = tid & 31;
    const int ms   = w & 3;
    const int nh   = w >> 2;
    const int g    = lane >> 2;
    const int tg   = lane & 3;

    // ---- pack fp16 weights into B-fragment layout Bpk[ks][nti][lane][2] ----
    uint32_t* Bpk = (uint32_t*)(smem + BPK_OFF);
    for (int idx = tid; idx < nks * 512; idx += NTH) {
        int j   = idx & 1;
        int ln  = (idx >> 1) & 31;
        int nti = (idx >> 6) & 7;
        int ks  = idx >> 9;
        int lg  = ln >> 2, ltg = ln & 3;
        int k   = ks * 16 + j * 8 + ltg * 2;
        int s   = 8 * nti + lg;
        int row = (s & 3) * HH + nt * 16 + (s >> 2);
        float w0, w1;
        if (k < K0) { w0 = WA[(size_t)row * K0 + k];        w1 = WA[(size_t)row * K0 + k + 1]; }
        else        { w0 = WB[(size_t)row * HH + (k - K0)]; w1 = WB[(size_t)row * HH + (k - K0) + 1]; }
        __half2 hw = __floats2half2_rn(w0, w1);
        Bpk[idx] = *(uint32_t*)&hw;
    }

    // ---- biases: 4 ntiles x 4 gates ----
    float biasr[4][4];
#pragma unroll
    for (int ntl = 0; ntl < 4; ntl++) {
        int ugl = nt * 16 + 8 * nh + 2 * ntl + (tg >> 1);
#pragma unroll
        for (int gt = 0; gt < 4; gt++)
            biasr[ntl][gt] = bA[gt * HH + ugl] + bB[gt * HH + ugl];
    }
    __syncthreads();   // Bpk ready

    const int lrow = ms * 16 + (lane & 7) + ((lane >> 3) & 1) * 8;
    const uint32_t rowoff = (uint32_t)(lrow * APITCH + ((lane >> 4) & 1) * 16);

    // epilogue roles
    const bool even = !(tg & 1);
    const int rl = ms * 16 + g + (even ? 0 : 8);
    const int rowg = mt * 64 + rl;

    float cst[4];
#pragma unroll
    for (int q = 0; q < 4; q++) cst[q] = 0.f;

    unsigned int* c0p = &g_c0a[mt];
    unsigned int* c1p = &g_c1a[mt];

    for (int step = 0; step < TT; step++) {
        StepCtx cx;
#pragma unroll
        for (int q = 0; q < 4; q++)
#pragma unroll
            for (int i = 0; i < 4; i++) cx.acc[q][i] = 0.f;

        __half* hout;
        if (layer == 0) {
            const __half* seg0 = g_xh + (size_t)step * II;
            const __half* seg1 = &g_h0[step & 3][0][0];
            hout = &g_h0[(step + 1) & 3][0][0];
            // chunk 0 is pure x -> issue before any wait
            issue_chunk(smb, 0, K0, seg0, (long)TT * II, seg1, mt, tid);
            wait_ge(c0p, 16 * step);                 // own group's prev h0
            issue_chunk(smb, 1, K0, seg0, (long)TT * II, seg1, mt, tid);
            issue_chunk(smb, 2, K0, seg0, (long)TT * II, seg1, mt, tid);
            compute_chunks(cx, smb, Bpk, rowoff, nh, lane, 3);
            wait_ge(c1p, 16 * (step - 3));           // anti-overwrite of h0 ring
        } else {
            const __half* seg0 = &g_h0[(step + 1) & 3][0][0];
            const __half* seg1 = &g_h1[step & 1][0][0];
            hout = &g_h1[(step + 1) & 1][0][0];
            wait_ge(c0p, 16 * (step + 1));           // layer0 finished this step
            wait_ge(c1p, 16 * step);                 // own group's prev h1
            issue_chunk(smb, 0, K0, seg0, HH, seg1, mt, tid);
            issue_chunk(smb, 1, K0, seg0, HH, seg1, mt, tid);
            issue_chunk(smb, 2, K0, seg0, HH, seg1, mt, tid);
            issue_chunk(smb, 3, K0, seg0, HH, seg1, mt, tid);
            compute_chunks(cx, smb, Bpk, rowoff, nh, lane, 4);
        }

        // epilogue: quad-exchange gates, activations, state update
#pragma unroll
        for (int ntl = 0; ntl < 4; ntl++) {
            float e0 = __shfl_xor_sync(0xffffffffu, cx.acc[ntl][0], 1);
            float e1 = __shfl_xor_sync(0xffffffffu, cx.acc[ntl][1], 1);
            float e2 = __shfl_xor_sync(0xffffffffu, cx.acc[ntl][2], 1);
            float e3 = __shfl_xor_sync(0xffffffffu, cx.acc[ntl][3], 1);
            float pi = (even ? cx.acc[ntl][0] : e2) + biasr[ntl][0];
            float pf = (even ? cx.acc[ntl][1] : e3) + biasr[ntl][1];
            float pg = (even ? e0 : cx.acc[ntl][2]) + biasr[ntl][2];
            float po = (even ? e1 : cx.acc[ntl][3]) + biasr[ntl][3];
            float cn = sigm_(pf) * cst[ntl] + sigm_(pi) * tanh_(pg);
            cst[ntl] = cn;
            float hv = sigm_(po) * tanh_(cn);
            int ug = nt * 16 + 8 * nh + 2 * ntl + (tg >> 1);
            hout[(size_t)rowg * HH + ug] = __float2half_rn(hv);
        }
        arrive(layer ? c1p : c0p);
    }
}

__global__ void convert_x(const float* __restrict__ x) {
    int idx = blockIdx.x * blockDim.x + threadIdx.x;
    int stride = gridDim.x * blockDim.x;
    if (idx < 4) { g_c0a[idx] = 0u; g_c1a[idx] = 0u; }
    __half2* dst = (__half2*)g_xh;
    const float2* src = (const float2*)x;
    for (int i = idx; i < BB * TT * II / 2; i += stride) {
        float2 v = src[i];
        dst[i] = __floats2half2_rn(v.x, v.y);
    }
    uint32_t* z0 = (uint32_t*)&g_h0[0][0][0];
    uint32_t* z1 = (uint32_t*)&g_h1[0][0][0];
    for (int i = idx; i < BB * HH / 2; i += stride) { z0[i] = 0u; z1[i] = 0u; }
}

// tiled classifier: out[256,1000] = h1 @ fcW^T + fcb
__global__ __launch_bounds__(256) void classifier2(
    const float* __restrict__ fcW, const float* __restrict__ fcb,
    float* __restrict__ out)
{
    __shared__ float hs[32][68];
    __shared__ float ws[32][68];
    const int bt = blockIdx.x;
    const int ct = blockIdx.y;
    const int tid = threadIdx.x;
    const int bq = tid >> 4, cq = tid & 15;
    float acc[4][4];
#pragma unroll
    for (int i = 0; i < 4; i++)
#pragma unroll
        for (int j = 0; j < 4; j++) acc[i][j] = 0.f;

    for (int k0 = 0; k0 < HH; k0 += 32) {
        __syncthreads();
        for (int i = tid; i < 64 * 32; i += 256) {
            int b = i >> 5, k = i & 31;
            hs[k][b] = __half2float(g_h1[0][bt * 64 + b][k0 + k]);
        }
        for (int i = tid; i < 64 * 32; i += 256) {
            int c = i >> 5, k = i & 31;
            int gc = ct * 64 + c;
            ws[k][c] = (gc < CC) ? fcW[(size_t)gc * HH + k0 + k] : 0.f;
        }
        __syncthreads();
#pragma unroll
        for (int k = 0; k < 32; k++) {
            float a[4], wv[4];
#pragma unroll
            for (int i = 0; i < 4; i++) a[i] = hs[k][bq * 4 + i];
#pragma unroll
            for (int j = 0; j < 4; j++) wv[j] = ws[k][cq * 4 + j];
#pragma unroll
            for (int i = 0; i < 4; i++)
#pragma unroll
                for (int j = 0; j < 4; j++)
                    acc[i][j] = fmaf(a[i], wv[j], acc[i][j]);
        }
    }
#pragma unroll
    for (int i = 0; i < 4; i++) {
        int b = bt * 64 + bq * 4 + i;
#pragma unroll
        for (int j = 0; j < 4; j++) {
            int c = ct * 64 + cq * 4 + j;
            if (c < CC) out[(size_t)b * CC + c] = acc[i][j] + fcb[c];
        }
    }
}

extern "C" void kernel_launch(void* const* d_in, const int* in_sizes, int n_in,
                              void* d_out, int out_size)
{
    const float* x    = (const float*)d_in[0];
    const float* Wih0 = (const float*)d_in[1];
    const float* Whh0 = (const float*)d_in[2];
    const float* bih0 = (const float*)d_in[3];
    const float* bhh0 = (const float*)d_in[4];
    const float* Wih1 = (const float*)d_in[5];
    const float* Whh1 = (const float*)d_in[6];
    const float* bih1 = (const float*)d_in[7];
    const float* bhh1 = (const float*)d_in[8];
    const float* fcW  = (const float*)d_in[9];
    const float* fcb  = (const float*)d_in[10];
    float* out = (float*)d_out;

    convert_x<<<4096, 256>>>(x);
    cudaFuncSetAttribute(lstm_mma, cudaFuncAttributeMaxDynamicSharedMemorySize, SMEM_BYTES);
    lstm_mma<<<NCTA, NTH, SMEM_BYTES>>>(Wih0, Whh0, bih0, bhh0,
                                        Wih1, Whh1, bih1, bhh1);
    classifier2<<<dim3(4, 16), 256>>>(fcW, fcb, out);
}